// round 2
// baseline (speedup 1.0000x reference)
#include <cuda_runtime.h>
#include <math.h>

#define Hh 160
#define Ww 480
#define HW 76800
#define NP 120000

typedef unsigned long long u64;

// ---------------- f32x2 packed helpers ----------------
__device__ __forceinline__ u64 pk(float x, float y) {
    u64 r; asm("mov.b64 %0, {%1,%2};" : "=l"(r) : "f"(x), "f"(y)); return r;
}
__device__ __forceinline__ u64 f2fma(u64 a, u64 b, u64 c) {
    u64 d; asm("fma.rn.f32x2 %0, %1, %2, %3;" : "=l"(d) : "l"(a), "l"(b), "l"(c)); return d;
}
__device__ __forceinline__ float hsum(u64 a) {
    float x, y; asm("mov.b64 {%0,%1}, %2;" : "=f"(x), "=f"(y) : "l"(a)); return x + y;
}

// ---------------- scratch (no allocations allowed) ----------------
__device__ int    d_win[3][HW];
__device__ int2   d_list[3][HW];
__device__ int    d_cnt[3];
__device__ float4 d_G0[9][16];    // folded red_w0 -> tap weights   [k][c/4]
__device__ float4 d_G1[9][32];    // folded red_w1 -> tap weights
__device__ float4 d_Wimg[9][64];  // sb_w[0:256]  transposed to [k][c/4]
__device__ float4 d_Wpt[9][64];   // sb_w[256:512] transposed to [k][o/4]
__device__ float  d_cb[9];        // folded bias constants per tap
__device__ float  d_ti[9][HW];    // image-part tap maps (incl cb)
__device__ float  d_tv[3][9][HW]; // voxel-part tap maps per level
__device__ __align__(16) float d_att[HW];

// ---------------- K0: fold 1x1 conv weights into the 3x3 taps ----------------
__global__ void k_prep(const float* __restrict__ rw0, const float* __restrict__ rb0,
                       const float* __restrict__ rw1, const float* __restrict__ rb1,
                       const float* __restrict__ sbw) {
    int k = blockIdx.x;      // tap 0..8
    int tid = threadIdx.x;   // 0..255
    ((float*)d_Wimg)[k * 256 + tid] = sbw[tid * 9 + k];
    ((float*)d_Wpt)[k * 256 + tid]  = sbw[(256 + tid) * 9 + k];
    if (tid < 64) {
        float s = 0.f;
        for (int o = 0; o < 256; o++) s += rw0[o * 64 + tid] * sbw[(256 + o) * 9 + k];
        ((float*)d_G0)[k * 64 + tid] = s;
    }
    if (tid < 128) {
        float s = 0.f;
        for (int o = 0; o < 256; o++) s += rw1[o * 128 + tid] * sbw[(256 + o) * 9 + k];
        ((float*)d_G1)[k * 128 + tid] = s;
    }
    if (tid == 0) {
        float s = 0.f;
        for (int o = 0; o < 256; o++) s += (rb0[o] + rb1[o]) * sbw[(256 + o) * 9 + k];
        d_cb[k] = s;
    }
}

// ---------------- K1: init winner maps, zero voxel tap planes ----------------
// 3*9*HW/4 float4 = 518400 -> 2025 blocks of 256
__global__ void k_init() {
    int i = blockIdx.x * 256 + threadIdx.x;
    ((float4*)d_tv)[i] = make_float4(0.f, 0.f, 0.f, 0.f);
    if (i < 3 * HW) ((int*)d_win)[i] = -1;
    if (i < 3) d_cnt[i] = 0;
}

// ---------------- K2: scatter, last-write-wins == max point index ----------------
__global__ void k_scatter(const int* __restrict__ g0, const int* __restrict__ g1,
                          const int* __restrict__ g2) {
    int i = blockIdx.x * blockDim.x + threadIdx.x;
    if (i >= 3 * NP) return;
    int lvl = i / NP;
    int p = i - lvl * NP;
    const int* g = (lvl == 0) ? g0 : ((lvl == 1) ? g1 : g2);
    int x = g[2 * p];
    int y = g[2 * p + 1];
    if (x >= 0 && x < Ww && y >= 0 && y < Hh)
        atomicMax(&d_win[lvl][y * Ww + x], p);
}

// ---------------- K3: compact winners into per-level lists ----------------
__global__ void k_compact() {
    int i = blockIdx.x * 256 + threadIdx.x;   // i < 3*HW (230400, divisible)
    int lvl = i / HW;
    int cell = i - lvl * HW;
    int p = d_win[lvl][cell];
    if (p >= 0) {
        int idx = atomicAdd(&d_cnt[lvl], 1);
        d_list[lvl][idx] = make_int2(cell, p);
    }
}

// ---------------- K4: image-part tap maps (pixel per thread) ----------------
__global__ void __launch_bounds__(256) k_img(const float* __restrict__ img,
                                             const float* __restrict__ seg) {
    __shared__ float4 sW[9 * 64];
    __shared__ float  scb[9];
    int tid = threadIdx.x;
    for (int i = tid; i < 576; i += 256) sW[i] = ((const float4*)d_Wimg)[i];
    if (tid < 9) scb[tid] = d_cb[tid];
    __syncthreads();

    int pix = blockIdx.x * 256 + tid;
    float s = seg[HW + pix];

    u64 acc[9];
#pragma unroll
    for (int k = 0; k < 9; k++) acc[k] = 0ull;

    const float* ip = img + pix;
#pragma unroll 4
    for (int c4 = 0; c4 < 64; c4++) {
        float a0 = ip[(size_t)(4 * c4 + 0) * HW];
        float a1 = ip[(size_t)(4 * c4 + 1) * HW];
        float a2 = ip[(size_t)(4 * c4 + 2) * HW];
        float a3 = ip[(size_t)(4 * c4 + 3) * HW];
        u64 lo = pk(a0, a1);
        u64 hi = pk(a2, a3);
#pragma unroll
        for (int k = 0; k < 9; k++) {
            float4 w = sW[k * 64 + c4];
            acc[k] = f2fma(lo, pk(w.x, w.y), acc[k]);
            acc[k] = f2fma(hi, pk(w.z, w.w), acc[k]);
        }
    }
#pragma unroll
    for (int k = 0; k < 9; k++) d_ti[k][pix] = scb[k] + s * hsum(acc[k]);
}

// ---------------- K5: voxel-part tap maps (point-major, coalesced gather) ----
// warp = 4 points x 8 channel-lanes; per-level winner lists; plain stores
template <int LVL, int C4>
__device__ __forceinline__ void voxel_body(const float* __restrict__ vf,
                                           float4* sw, int* s_n, int blk) {
    int tid = threadIdx.x;
    if (tid == 0) *s_n = d_cnt[LVL];
    const float4* wsrc = (LVL == 0) ? (const float4*)d_G0
                        : (LVL == 1) ? (const float4*)d_G1
                                     : (const float4*)d_Wpt;
    for (int i = tid; i < 9 * C4; i += 256) sw[i] = wsrc[i];
    __syncthreads();
    int n = *s_n;
    int base = blk * 32;
    if (base >= n) return;

    int lane = tid & 31;
    int w    = tid >> 5;
    int sub  = lane >> 3;   // point within warp (0..3)
    int cs   = lane & 7;    // channel lane (0..7)

    int idx = base + w * 4 + sub;
    bool valid = idx < n;
    int2 e = valid ? d_list[LVL][idx] : make_int2(0, 0);
    const float4* row = (const float4*)vf + (size_t)e.y * C4;

    u64 acc[9];
#pragma unroll
    for (int k = 0; k < 9; k++) acc[k] = 0ull;

#pragma unroll
    for (int m = 0; m < C4 / 8; m++) {
        int c4 = cs + 8 * m;
        float4 v = row[c4];           // invalid lanes read row 0 (safe), results masked
        u64 vlo = pk(v.x, v.y);
        u64 vhi = pk(v.z, v.w);
#pragma unroll
        for (int k = 0; k < 9; k++) {
            float4 wv = sw[k * C4 + c4];
            acc[k] = f2fma(vlo, pk(wv.x, wv.y), acc[k]);
            acc[k] = f2fma(vhi, pk(wv.z, wv.w), acc[k]);
        }
    }
#pragma unroll
    for (int k = 0; k < 9; k++) {
        float s = hsum(acc[k]);
        s += __shfl_xor_sync(0xffffffffu, s, 1);
        s += __shfl_xor_sync(0xffffffffu, s, 2);
        s += __shfl_xor_sync(0xffffffffu, s, 4);
        if (cs == 0 && valid) d_tv[LVL][k][e.x] = s;
    }
}

__global__ void __launch_bounds__(256) k_voxel(const float* __restrict__ vf0,
                                               const float* __restrict__ vf1,
                                               const float* __restrict__ vf2) {
    __shared__ float4 sw[9 * 64];
    __shared__ int s_n;
    int b = blockIdx.x;
    if (b < 2400)      voxel_body<0, 16>(vf0, sw, &s_n, b);
    else if (b < 4800) voxel_body<1, 32>(vf1, sw, &s_n, b - 2400);
    else               voxel_body<2, 64>(vf2, sw, &s_n, b - 4800);
}

// ---------------- K6: combine shifted tap maps -> sigmoid -> fold seg gate ----
__global__ void k_att(const float* __restrict__ seg, const float* __restrict__ sbb) {
    int pix = blockIdx.x * 256 + threadIdx.x;
    int y = pix / Ww;
    int x = pix - y * Ww;
    float sum = sbb[0];
#pragma unroll
    for (int ky = 0; ky < 3; ky++) {
        int yy = y + ky - 1;
        if (yy < 0 || yy >= Hh) continue;
#pragma unroll
        for (int kx = 0; kx < 3; kx++) {
            int xx = x + kx - 1;
            if (xx < 0 || xx >= Ww) continue;
            int kk = ky * 3 + kx;
            int ni = yy * Ww + xx;
            sum += d_ti[kk][ni] + d_tv[0][kk][ni] + d_tv[1][kk][ni] + d_tv[2][kk][ni];
        }
    }
    float att = 1.f / (1.f + expf(-sum));
    d_att[pix] = att * seg[HW + pix];
}

// ---------------- K7: out = img * (seg * attention), pure stream ----------------
__global__ void k_out(const float4* __restrict__ img, float4* __restrict__ out) {
    int i = blockIdx.x * 256 + threadIdx.x;  // float4 index, total 256*HW/4
    int pix4 = i % (HW / 4);
    float4 a = *(const float4*)(&d_att[pix4 * 4]);
    float4 im = img[i];
    float4 o;
    o.x = im.x * a.x;
    o.y = im.y * a.y;
    o.z = im.z * a.z;
    o.w = im.w * a.w;
    out[i] = o;
}

extern "C" void kernel_launch(void* const* d_in, const int* in_sizes, int n_in,
                              void* d_out, int out_size) {
    const float* img = (const float*)d_in[0];
    const float* seg = (const float*)d_in[1];

    int iv0, iv1, iv2, ig0, ig1, ig2;
    if (in_sizes[3] == 2 * NP) { iv0 = 2; ig0 = 3; iv1 = 4; ig1 = 5; iv2 = 6; ig2 = 7; }
    else                       { iv0 = 2; iv1 = 3; iv2 = 4; ig0 = 5; ig1 = 6; ig2 = 7; }

    const float* vf0 = (const float*)d_in[iv0];
    const float* vf1 = (const float*)d_in[iv1];
    const float* vf2 = (const float*)d_in[iv2];
    const int*   g0  = (const int*)d_in[ig0];
    const int*   g1  = (const int*)d_in[ig1];
    const int*   g2  = (const int*)d_in[ig2];
    const float* rw0 = (const float*)d_in[8];
    const float* rb0 = (const float*)d_in[9];
    const float* rw1 = (const float*)d_in[10];
    const float* rb1 = (const float*)d_in[11];
    const float* sbw = (const float*)d_in[12];
    const float* sbb = (const float*)d_in[13];

    k_prep<<<9, 256>>>(rw0, rb0, rw1, rb1, sbw);
    k_init<<<2025, 256>>>();
    k_scatter<<<(3 * NP + 255) / 256, 256>>>(g0, g1, g2);
    k_compact<<<(3 * HW) / 256, 256>>>();
    k_img<<<HW / 256, 256>>>(img, seg);
    k_voxel<<<7200, 256>>>(vf0, vf1, vf2);
    k_att<<<HW / 256, 256>>>(seg, sbb);
    k_out<<<(256 * HW / 4) / 256, 256>>>((const float4*)img, (float4*)d_out);
}

// round 3
// speedup vs baseline: 1.8477x; 1.8477x over previous
#include <cuda_runtime.h>
#include <math.h>

#define Hh 160
#define Ww 480
#define HW 76800
#define NP 120000

typedef unsigned long long u64;

// ---------------- f32x2 packed helpers ----------------
__device__ __forceinline__ u64 pk(float x, float y) {
    u64 r; asm("mov.b64 %0, {%1,%2};" : "=l"(r) : "f"(x), "f"(y)); return r;
}
__device__ __forceinline__ u64 f2fma(u64 a, u64 b, u64 c) {
    u64 d; asm("fma.rn.f32x2 %0, %1, %2, %3;" : "=l"(d) : "l"(a), "l"(b), "l"(c)); return d;
}
__device__ __forceinline__ float hsum(u64 a) {
    float x, y; asm("mov.b64 {%0,%1}, %2;" : "=f"(x), "=f"(y) : "l"(a)); return x + y;
}

// ---------------- scratch (no allocations allowed) ----------------
__device__ int    d_win[3][HW];
__device__ int2   d_list[3][HW];
__device__ int    d_cnt[3];
__device__ float4 d_G0[9][16];    // folded red_w0 -> tap weights   [k][c/4]
__device__ float4 d_G1[9][32];    // folded red_w1 -> tap weights
__device__ float4 d_Wimg[9][64];  // sb_w[0:256]  transposed to [k][c/4]
__device__ float4 d_Wpt[9][64];   // sb_w[256:512] transposed to [k][o/4]
__device__ float  d_cb[9];        // folded bias constants per tap
__device__ float  d_ti[9][HW];    // image-part tap maps (incl cb)
__device__ float  d_tv[3][9][HW]; // voxel-part tap maps per level

// ---------------- K0: prep (blocks 0..8) + init (blocks 9..2033) -------------
__global__ void k_initprep(const float* __restrict__ rw0, const float* __restrict__ rb0,
                           const float* __restrict__ rw1, const float* __restrict__ rb1,
                           const float* __restrict__ sbw) {
    int b = blockIdx.x;
    int tid = threadIdx.x;
    if (b < 9) {
        int k = b;
        ((float*)d_Wimg)[k * 256 + tid] = sbw[tid * 9 + k];
        ((float*)d_Wpt)[k * 256 + tid]  = sbw[(256 + tid) * 9 + k];
        if (tid < 64) {
            float s = 0.f;
            for (int o = 0; o < 256; o++) s += rw0[o * 64 + tid] * sbw[(256 + o) * 9 + k];
            ((float*)d_G0)[k * 64 + tid] = s;
        }
        if (tid < 128) {
            float s = 0.f;
            for (int o = 0; o < 256; o++) s += rw1[o * 128 + tid] * sbw[(256 + o) * 9 + k];
            ((float*)d_G1)[k * 128 + tid] = s;
        }
        if (tid == 0) {
            float s = 0.f;
            for (int o = 0; o < 256; o++) s += (rb0[o] + rb1[o]) * sbw[(256 + o) * 9 + k];
            d_cb[k] = s;
        }
    } else {
        int i = (b - 9) * 256 + tid;          // 0 .. 518399
        ((float4*)d_tv)[i] = make_float4(0.f, 0.f, 0.f, 0.f);
        if (i < 3 * HW) ((int*)d_win)[i] = -1;
        if (i < 3) d_cnt[i] = 0;
    }
}

// ---------------- K1: scatter, last-write-wins == max point index ------------
__global__ void k_scatter(const int* __restrict__ g0, const int* __restrict__ g1,
                          const int* __restrict__ g2) {
    int i = blockIdx.x * blockDim.x + threadIdx.x;
    if (i >= 3 * NP) return;
    int lvl = i / NP;
    int p = i - lvl * NP;
    const int* g = (lvl == 0) ? g0 : ((lvl == 1) ? g1 : g2);
    int x = g[2 * p];
    int y = g[2 * p + 1];
    if (x >= 0 && x < Ww && y >= 0 && y < Hh)
        atomicMax(&d_win[lvl][y * Ww + x], p);
}

// ---------------- K2: hierarchical compaction (1 global atomic / block) ------
__global__ void k_compact() {
    int lvl = blockIdx.x / 300;
    int cell = (blockIdx.x % 300) * 256 + threadIdx.x;
    int p = d_win[lvl][cell];
    bool valid = p >= 0;
    unsigned m = __ballot_sync(0xffffffffu, valid);
    int lane = threadIdx.x & 31;
    int wid = threadIdx.x >> 5;
    __shared__ int wbase[8];
    __shared__ int sbase;
    if (lane == 0) wbase[wid] = __popc(m);
    __syncthreads();
    if (threadIdx.x == 0) {
        int tot = 0;
#pragma unroll
        for (int i = 0; i < 8; i++) { int c = wbase[i]; wbase[i] = tot; tot += c; }
        sbase = atomicAdd(&d_cnt[lvl], tot);
    }
    __syncthreads();
    if (valid) {
        int pos = sbase + wbase[wid] + __popc(m & ((1u << lane) - 1));
        d_list[lvl][pos] = make_int2(cell, p);
    }
}

// ---------------- K3 bodies: image part + voxel part --------------------------
__device__ __forceinline__ void img_body(const float* __restrict__ img,
                                         const float* __restrict__ seg,
                                         float4* sW, int blk) {
    int tid = threadIdx.x;
    for (int i = tid; i < 576; i += 256) sW[i] = ((const float4*)d_Wimg)[i];
    __shared__ float scb[9];
    if (tid < 9) scb[tid] = d_cb[tid];
    __syncthreads();

    int pix = blk * 256 + tid;
    float s = seg[HW + pix];

    u64 acc[9];
#pragma unroll
    for (int k = 0; k < 9; k++) acc[k] = 0ull;

    const float* ip = img + pix;
#pragma unroll 4
    for (int c4 = 0; c4 < 64; c4++) {
        float a0 = ip[(size_t)(4 * c4 + 0) * HW];
        float a1 = ip[(size_t)(4 * c4 + 1) * HW];
        float a2 = ip[(size_t)(4 * c4 + 2) * HW];
        float a3 = ip[(size_t)(4 * c4 + 3) * HW];
        u64 lo = pk(a0, a1);
        u64 hi = pk(a2, a3);
#pragma unroll
        for (int k = 0; k < 9; k++) {
            float4 w = sW[k * 64 + c4];
            acc[k] = f2fma(lo, pk(w.x, w.y), acc[k]);
            acc[k] = f2fma(hi, pk(w.z, w.w), acc[k]);
        }
    }
#pragma unroll
    for (int k = 0; k < 9; k++) d_ti[k][pix] = scb[k] + s * hsum(acc[k]);
}

// warp = 4 points x 8 channel-lanes; per-level winner lists; plain stores
template <int LVL, int C4>
__device__ __forceinline__ void voxel_body(const float* __restrict__ vf,
                                           float4* sw, int blk) {
    int n = d_cnt[LVL];
    int base = blk * 32;
    if (base >= n) return;

    int tid = threadIdx.x;
    const float4* wsrc = (LVL == 0) ? (const float4*)d_G0
                        : (LVL == 1) ? (const float4*)d_G1
                                     : (const float4*)d_Wpt;
    for (int i = tid; i < 9 * C4; i += 256) sw[i] = wsrc[i];
    __syncthreads();

    int lane = tid & 31;
    int w    = tid >> 5;
    int sub  = lane >> 3;   // point within warp (0..3)
    int cs   = lane & 7;    // channel lane (0..7)

    int idx = base + w * 4 + sub;
    bool valid = idx < n;
    int2 e = valid ? d_list[LVL][idx] : make_int2(0, 0);
    const float4* row = (const float4*)vf + (size_t)e.y * C4;

    u64 acc[9];
#pragma unroll
    for (int k = 0; k < 9; k++) acc[k] = 0ull;

#pragma unroll
    for (int m = 0; m < C4 / 8; m++) {
        int c4 = cs + 8 * m;
        float4 v = row[c4];           // invalid lanes read row 0 (safe), masked below
        u64 vlo = pk(v.x, v.y);
        u64 vhi = pk(v.z, v.w);
#pragma unroll
        for (int k = 0; k < 9; k++) {
            float4 wv = sw[k * C4 + c4];
            acc[k] = f2fma(vlo, pk(wv.x, wv.y), acc[k]);
            acc[k] = f2fma(vhi, pk(wv.z, wv.w), acc[k]);
        }
    }
#pragma unroll
    for (int k = 0; k < 9; k++) {
        float s = hsum(acc[k]);
        s += __shfl_xor_sync(0xffffffffu, s, 1);
        s += __shfl_xor_sync(0xffffffffu, s, 2);
        s += __shfl_xor_sync(0xffffffffu, s, 4);
        if (cs == 0 && valid) d_tv[LVL][k][e.x] = s;
    }
}

// ---------------- K3: merged work kernel --------------------------------------
// blocks [0,2400): lvl2   [2400,4800): lvl1   [4800,7200): lvl0   [7200,7500): img
__global__ void __launch_bounds__(256) k_work(const float* __restrict__ img,
                                              const float* __restrict__ seg,
                                              const float* __restrict__ vf0,
                                              const float* __restrict__ vf1,
                                              const float* __restrict__ vf2) {
    __shared__ float4 sw[9 * 64];
    int b = blockIdx.x;
    if (b < 2400)      voxel_body<2, 64>(vf2, sw, b);
    else if (b < 4800) voxel_body<1, 32>(vf1, sw, b - 2400);
    else if (b < 7200) voxel_body<0, 16>(vf0, sw, b - 4800);
    else               img_body(img, seg, sw, b - 7200);
}

// ---------------- K4: att (into smem) + gated output stream -------------------
__global__ void __launch_bounds__(256) k_attout(const float* __restrict__ img,
                                                const float* __restrict__ seg,
                                                const float* __restrict__ sbb,
                                                float* __restrict__ out) {
    __shared__ __align__(16) float satt[256];
    int tid = threadIdx.x;
    int base = blockIdx.x * 256;
    int pix = base + tid;
    {
        int y = pix / Ww;
        int x = pix - y * Ww;
        float sum = sbb[0];
#pragma unroll
        for (int ky = 0; ky < 3; ky++) {
            int yy = y + ky - 1;
            if (yy < 0 || yy >= Hh) continue;
#pragma unroll
            for (int kx = 0; kx < 3; kx++) {
                int xx = x + kx - 1;
                if (xx < 0 || xx >= Ww) continue;
                int kk = ky * 3 + kx;
                int ni = yy * Ww + xx;
                sum += d_ti[kk][ni] + d_tv[0][kk][ni] + d_tv[1][kk][ni] + d_tv[2][kk][ni];
            }
        }
        float att = 1.f / (1.f + expf(-sum));
        satt[tid] = att * seg[HW + pix];
    }
    __syncthreads();

    // stream all 256 channels for this block's 256 pixels (64 float4 per channel)
    int q = tid & 63;          // pixel-quad within block
    int c0 = tid >> 6;         // starting channel (0..3)
    float4 a = ((const float4*)satt)[q];
    const float4* im4 = (const float4*)img;
    float4* o4 = (float4*)out;
    size_t idx = (size_t)c0 * (HW / 4) + (base / 4) + q;
#pragma unroll 8
    for (int c = c0; c < 256; c += 4, idx += (size_t)4 * (HW / 4)) {
        float4 v = im4[idx];
        v.x *= a.x; v.y *= a.y; v.z *= a.z; v.w *= a.w;
        o4[idx] = v;
    }
}

extern "C" void kernel_launch(void* const* d_in, const int* in_sizes, int n_in,
                              void* d_out, int out_size) {
    const float* img = (const float*)d_in[0];
    const float* seg = (const float*)d_in[1];

    int iv0, iv1, iv2, ig0, ig1, ig2;
    if (in_sizes[3] == 2 * NP) { iv0 = 2; ig0 = 3; iv1 = 4; ig1 = 5; iv2 = 6; ig2 = 7; }
    else                       { iv0 = 2; iv1 = 3; iv2 = 4; ig0 = 5; ig1 = 6; ig2 = 7; }

    const float* vf0 = (const float*)d_in[iv0];
    const float* vf1 = (const float*)d_in[iv1];
    const float* vf2 = (const float*)d_in[iv2];
    const int*   g0  = (const int*)d_in[ig0];
    const int*   g1  = (const int*)d_in[ig1];
    const int*   g2  = (const int*)d_in[ig2];
    const float* rw0 = (const float*)d_in[8];
    const float* rb0 = (const float*)d_in[9];
    const float* rw1 = (const float*)d_in[10];
    const float* rb1 = (const float*)d_in[11];
    const float* sbw = (const float*)d_in[12];
    const float* sbb = (const float*)d_in[13];

    k_initprep<<<2034, 256>>>(rw0, rb0, rw1, rb1, sbw);
    k_scatter<<<(3 * NP + 255) / 256, 256>>>(g0, g1, g2);
    k_compact<<<900, 256>>>();
    k_work<<<7500, 256>>>(img, seg, vf0, vf1, vf2);
    k_attout<<<HW / 256, 256>>>(img, seg, sbb, (float*)d_out);
}